// round 9
// baseline (speedup 1.0000x reference)
#include <cuda_runtime.h>
#include <math.h>

#define B_ 4
#define C_ 512
#define L_ 2048
#define H_ 8
#define D_ 64
#define G_ 8
#define CPG_ (C_/G_)
#define EPS_ 1e-5f

// ---------------- scratch (fp32 only, proven pattern) ------------------------
__device__ float g_s[B_ * C_];
__device__ float g_t[B_ * C_];
__device__ float g_qkv[(size_t)B_ * 3 * C_ * L_];      // 50 MB
__device__ float g_att[(size_t)B_ * C_ * L_];          // 17 MB

// ---------------- fast exp ---------------------------------------------------
__device__ __forceinline__ float fast_exp(float x) {
    float z = x * 1.4426950408889634f;
    z = fmaxf(z, -126.0f);
    float zi = rintf(z);
    int   i  = (int)zi;
    float y  = (z - zi) * 0.6931471805599453f;
    float r  = 8.3333333e-3f;
    r = fmaf(r, y, 4.1666667e-2f);
    r = fmaf(r, y, 1.6666667e-1f);
    r = fmaf(r, y, 0.5f);
    r = fmaf(r, y, 1.0f);
    r = fmaf(r, y, 1.0f);
    return __int_as_float(__float_as_int(r) + (i << 23));
}

// ---------------- 1) GroupNorm stats (verbatim from passing R2) --------------
__global__ __launch_bounds__(256) void gn_stats_kernel(
    const float* __restrict__ x, const float* __restrict__ nw,
    const float* __restrict__ nb)
{
    int bg = blockIdx.x;
    int b = bg / G_, g = bg % G_;
    const float* xp = x + ((size_t)b * C_ + (size_t)g * CPG_) * L_;
    const int NE = CPG_ * L_;
    float sum = 0.f, sq = 0.f;
    for (int i = threadIdx.x; i < NE; i += 256) {
        float v = xp[i];
        sum += v; sq = fmaf(v, v, sq);
    }
    __shared__ float ssum[256], ssq[256];
    ssum[threadIdx.x] = sum; ssq[threadIdx.x] = sq;
    __syncthreads();
    for (int off = 128; off > 0; off >>= 1) {
        if (threadIdx.x < off) {
            ssum[threadIdx.x] += ssum[threadIdx.x + off];
            ssq[threadIdx.x]  += ssq[threadIdx.x + off];
        }
        __syncthreads();
    }
    float mean = ssum[0] * (1.0f / NE);
    float var  = ssq[0] * (1.0f / NE) - mean * mean;
    float rstd = rsqrtf(var + EPS_);
    if (threadIdx.x < CPG_) {
        int c = g * CPG_ + threadIdx.x;
        float s = nw[c] * rstd;
        g_s[b * C_ + c] = s;
        g_t[b * C_ + c] = nb[c] - mean * s;
    }
}

// ---------------- 2) SGEMM (verbatim from passing R2) ------------------------
template<bool FOLD, bool RESID>
__global__ __launch_bounds__(256) void sgemm_wx_kernel(
    const float* __restrict__ A, const float* __restrict__ Bm,
    const float* __restrict__ bias, const float* __restrict__ resid,
    float* __restrict__ Cm, int M, int N, int K)
{
    int bz = blockIdx.z;
    const float* Bp = Bm + (size_t)bz * K * N;
    float*       Cp = Cm + (size_t)bz * M * N;
    const float* Rp = RESID ? (resid + (size_t)bz * M * N) : nullptr;
    const float* sp = FOLD ? (g_s + bz * C_) : nullptr;
    const float* tp = FOLD ? (g_t + bz * C_) : nullptr;

    int m0 = blockIdx.y * 128, n0 = blockIdx.x * 128;
    __shared__ float As[8][128];
    __shared__ float Bs[8][128];

    int tid = threadIdx.x;
    int tx = tid % 16, ty = tid / 16;
    int ar = tid / 2,  ac = (tid % 2) * 4;
    int bk = tid / 32, bn = (tid % 32) * 4;

    float acc[8][8];
#pragma unroll
    for (int i = 0; i < 8; i++)
#pragma unroll
        for (int j = 0; j < 8; j++) acc[i][j] = 0.f;

    for (int k0 = 0; k0 < K; k0 += 8) {
        float4 av = *(const float4*)&A[(size_t)(m0 + ar) * K + k0 + ac];
        float4 bv = *(const float4*)&Bp[(size_t)(k0 + bk) * N + n0 + bn];
        if (FOLD) {
            float ss = sp[k0 + bk], tt = tp[k0 + bk];
            bv.x = fmaf(bv.x, ss, tt); bv.y = fmaf(bv.y, ss, tt);
            bv.z = fmaf(bv.z, ss, tt); bv.w = fmaf(bv.w, ss, tt);
        }
        __syncthreads();
        As[ac + 0][ar] = av.x; As[ac + 1][ar] = av.y;
        As[ac + 2][ar] = av.z; As[ac + 3][ar] = av.w;
        *(float4*)&Bs[bk][bn] = bv;
        __syncthreads();
#pragma unroll
        for (int kk = 0; kk < 8; kk++) {
            float a[8], bb[8];
            *(float4*)&a[0]  = *(const float4*)&As[kk][ty * 8];
            *(float4*)&a[4]  = *(const float4*)&As[kk][ty * 8 + 4];
            *(float4*)&bb[0] = *(const float4*)&Bs[kk][tx * 8];
            *(float4*)&bb[4] = *(const float4*)&Bs[kk][tx * 8 + 4];
#pragma unroll
            for (int i = 0; i < 8; i++)
#pragma unroll
                for (int j = 0; j < 8; j++)
                    acc[i][j] = fmaf(a[i], bb[j], acc[i][j]);
        }
    }

#pragma unroll
    for (int i = 0; i < 8; i++) {
        int m = m0 + ty * 8 + i;
        float bvv = bias[m];
        size_t base = (size_t)m * N + n0 + tx * 8;
#pragma unroll
        for (int v = 0; v < 2; v++) {
            float4 o;
            o.x = acc[i][v * 4 + 0] + bvv; o.y = acc[i][v * 4 + 1] + bvv;
            o.z = acc[i][v * 4 + 2] + bvv; o.w = acc[i][v * 4 + 3] + bvv;
            if (RESID) {
                float4 r = *(const float4*)&Rp[base + v * 4];
                o.x += r.x; o.y += r.y; o.z += r.z; o.w += r.w;
            }
            *(float4*)&Cp[base + v * 4] = o;
        }
    }
}

// ---------------- 3) fused flash attention (fp32, online softmax) ------------
// CTA: 64 q-rows, loop over keys in blocks of 32. 256 thr = 64 rows x 4.
__global__ __launch_bounds__(256) void flash_kernel()
{
    __shared__ __align__(16) float qS[64][68];
    __shared__ __align__(16) float kS[32][68];
    __shared__ __align__(16) float vS[32][68];
    __shared__ __align__(16) float Psm[64][36];
    __shared__ float red[64][4];

    int z = blockIdx.y, b = z / H_, h = z % H_;
    int l0 = blockIdx.x * 64;
    const float* qp = g_qkv + (size_t)b * 3 * C_ * L_ + (size_t)(h * D_) * L_;
    const float* kp = qp + (size_t)C_ * L_;
    const float* vp = kp + (size_t)C_ * L_;

    int tid = threadIdx.x;
    int l = tid >> 2, td = tid & 3;

    // q tile (transpose to [l][d]); fold scale D^-1/2 = 0.125 into q
    for (int e = tid; e < 64 * 64; e += 256) {
        int d = e >> 6, ll = e & 63;
        qS[ll][d] = qp[(size_t)d * L_ + l0 + ll] * 0.125f;
    }
    __syncthreads();

    float out[16];
#pragma unroll
    for (int j = 0; j < 16; j++) out[j] = 0.f;
    float mx = -1e30f, sml = 0.f;

    for (int m0 = 0; m0 < L_; m0 += 32) {
        // load k,v tiles [m][d] (coalesced along m)
        for (int e = tid; e < 32 * 64; e += 256) {
            int d = e >> 5, mm = e & 31;
            kS[mm][d] = kp[(size_t)d * L_ + m0 + mm];
            vS[mm][d] = vp[(size_t)d * L_ + m0 + mm];
        }
        __syncthreads();

        // S: this thread covers m = mm*4 + td for mm in 0..7
        float s[8];
#pragma unroll
        for (int mm = 0; mm < 8; mm++) s[mm] = 0.f;
        for (int d0 = 0; d0 < 64; d0 += 4) {
            float4 qf = *(const float4*)&qS[l][d0];
#pragma unroll
            for (int mm = 0; mm < 8; mm++) {
                float4 kf = *(const float4*)&kS[mm * 4 + td][d0];
                s[mm] = fmaf(qf.x, kf.x, s[mm]);
                s[mm] = fmaf(qf.y, kf.y, s[mm]);
                s[mm] = fmaf(qf.z, kf.z, s[mm]);
                s[mm] = fmaf(qf.w, kf.w, s[mm]);
            }
        }

        // online softmax
        float tm = s[0];
#pragma unroll
        for (int mm = 1; mm < 8; mm++) tm = fmaxf(tm, s[mm]);
        red[l][td] = tm;
        __syncthreads();
        float nm = fmaxf(fmaxf(red[l][0], red[l][1]), fmaxf(red[l][2], red[l][3]));
        nm = fmaxf(nm, mx);
        float alpha = fast_exp(mx - nm);
        mx = nm;
        float ps = 0.f;
#pragma unroll
        for (int mm = 0; mm < 8; mm++) {
            float p = fast_exp(s[mm] - nm);
            ps += p;
            Psm[l][mm * 4 + td] = p;
        }
        sml = fmaf(sml, alpha, ps);
#pragma unroll
        for (int j = 0; j < 16; j++) out[j] *= alpha;
        __syncthreads();

        // PV: out[j*4+q] for d = td*4 + 16*j + q
#pragma unroll 4
        for (int m = 0; m < 32; m++) {
            float p = Psm[l][m];
#pragma unroll
            for (int j = 0; j < 4; j++) {
                float4 vf = *(const float4*)&vS[m][td * 4 + 16 * j];
                out[j * 4 + 0] = fmaf(p, vf.x, out[j * 4 + 0]);
                out[j * 4 + 1] = fmaf(p, vf.y, out[j * 4 + 1]);
                out[j * 4 + 2] = fmaf(p, vf.z, out[j * 4 + 2]);
                out[j * 4 + 3] = fmaf(p, vf.w, out[j * 4 + 3]);
            }
        }
        __syncthreads();
    }

    // final normalize + store to att[d][l]
    red[l][td] = sml;
    __syncthreads();
    float inv = 1.0f / (red[l][0] + red[l][1] + red[l][2] + red[l][3]);
    float* op = g_att + (size_t)b * C_ * L_ + (size_t)(h * D_) * L_;
#pragma unroll
    for (int j = 0; j < 4; j++) {
#pragma unroll
        for (int q = 0; q < 4; q++) {
            int d = td * 4 + 16 * j + q;
            op[(size_t)d * L_ + l0 + l] = out[j * 4 + q] * inv;
        }
    }
}

// ---------------- launch -----------------------------------------------------
extern "C" void kernel_launch(void* const* d_in, const int* in_sizes, int n_in,
                              void* d_out, int out_size)
{
    const float* x      = (const float*)d_in[0];
    const float* norm_w = (const float*)d_in[1];
    const float* norm_b = (const float*)d_in[2];
    const float* qkv_w  = (const float*)d_in[3];
    const float* qkv_b  = (const float*)d_in[4];
    const float* proj_w = (const float*)d_in[5];
    const float* proj_b = (const float*)d_in[6];
    float* out = (float*)d_out;

    float* qkv_ptr; cudaGetSymbolAddress((void**)&qkv_ptr, g_qkv);
    float* att_ptr; cudaGetSymbolAddress((void**)&att_ptr, g_att);

    // 1) groupnorm stats
    gn_stats_kernel<<<B_ * G_, 256>>>(x, norm_w, norm_b);

    // 2) qkv = W_qkv @ gn(x) + b
    {
        dim3 grid(L_ / 128, (3 * C_) / 128, B_);
        sgemm_wx_kernel<true, false><<<grid, 256>>>(
            qkv_w, x, qkv_b, nullptr, qkv_ptr, 3 * C_, L_, C_);
    }

    // 3) fused attention (scores + softmax + AV)
    {
        dim3 grid(L_ / 64, B_ * H_);
        flash_kernel<<<grid, 256>>>();
    }

    // 4) proj + bias + residual
    {
        dim3 grid(L_ / 128, C_ / 128, B_);
        sgemm_wx_kernel<false, true><<<grid, 256>>>(
            proj_w, att_ptr, proj_b, x, out, C_, L_, C_);
    }
}

// round 12
// speedup vs baseline: 1.9121x; 1.9121x over previous
#include <cuda_runtime.h>
#include <math.h>

#define B_ 4
#define C_ 512
#define L_ 2048
#define H_ 8
#define D_ 64
#define G_ 8
#define CPG_ (C_/G_)
#define EPS_ 1e-5f

// ---------------- scratch ----------------------------------------------------
__device__ float g_s[B_ * C_];
__device__ float g_t[B_ * C_];
__device__ float g_qkv[(size_t)B_ * 3 * C_ * L_];
__device__ float g_att[(size_t)B_ * C_ * L_];

// ---------------- fast exp ---------------------------------------------------
__device__ __forceinline__ float fast_exp(float x) {
    float z = x * 1.4426950408889634f;
    z = fmaxf(z, -126.0f);
    float zi = rintf(z);
    int   i  = (int)zi;
    float y  = (z - zi) * 0.6931471805599453f;
    float r  = 8.3333333e-3f;
    r = fmaf(r, y, 4.1666667e-2f);
    r = fmaf(r, y, 1.6666667e-1f);
    r = fmaf(r, y, 0.5f);
    r = fmaf(r, y, 1.0f);
    r = fmaf(r, y, 1.0f);
    return __int_as_float(__float_as_int(r) + (i << 23));
}

// ---------------- 1) GroupNorm stats (proven) --------------------------------
__global__ __launch_bounds__(256) void gn_stats_kernel(
    const float* __restrict__ x, const float* __restrict__ nw,
    const float* __restrict__ nb)
{
    int bg = blockIdx.x;
    int b = bg / G_, g = bg % G_;
    const float* xp = x + ((size_t)b * C_ + (size_t)g * CPG_) * L_;
    const int NE = CPG_ * L_;
    float sum = 0.f, sq = 0.f;
    for (int i = threadIdx.x; i < NE; i += 256) {
        float v = xp[i];
        sum += v; sq = fmaf(v, v, sq);
    }
    __shared__ float ssum[256], ssq[256];
    ssum[threadIdx.x] = sum; ssq[threadIdx.x] = sq;
    __syncthreads();
    for (int off = 128; off > 0; off >>= 1) {
        if (threadIdx.x < off) {
            ssum[threadIdx.x] += ssum[threadIdx.x + off];
            ssq[threadIdx.x]  += ssq[threadIdx.x + off];
        }
        __syncthreads();
    }
    float mean = ssum[0] * (1.0f / NE);
    float var  = ssq[0] * (1.0f / NE) - mean * mean;
    float rstd = rsqrtf(var + EPS_);
    if (threadIdx.x < CPG_) {
        int c = g * CPG_ + threadIdx.x;
        float s = nw[c] * rstd;
        g_s[b * C_ + c] = s;
        g_t[b * C_ + c] = nb[c] - mean * s;
    }
}

// ---------------- 2) SGEMM (proven, verbatim) --------------------------------
template<bool FOLD, bool RESID>
__global__ __launch_bounds__(256) void sgemm_wx_kernel(
    const float* __restrict__ A, const float* __restrict__ Bm,
    const float* __restrict__ bias, const float* __restrict__ resid,
    float* __restrict__ Cm, int M, int N, int K)
{
    int bz = blockIdx.z;
    const float* Bp = Bm + (size_t)bz * K * N;
    float*       Cp = Cm + (size_t)bz * M * N;
    const float* Rp = RESID ? (resid + (size_t)bz * M * N) : nullptr;
    const float* sp = FOLD ? (g_s + bz * C_) : nullptr;
    const float* tp = FOLD ? (g_t + bz * C_) : nullptr;

    int m0 = blockIdx.y * 128, n0 = blockIdx.x * 128;
    __shared__ float As[8][128];
    __shared__ float Bs[8][128];

    int tid = threadIdx.x;
    int tx = tid % 16, ty = tid / 16;
    int ar = tid / 2,  ac = (tid % 2) * 4;
    int bk = tid / 32, bn = (tid % 32) * 4;

    float acc[8][8];
#pragma unroll
    for (int i = 0; i < 8; i++)
#pragma unroll
        for (int j = 0; j < 8; j++) acc[i][j] = 0.f;

    for (int k0 = 0; k0 < K; k0 += 8) {
        float4 av = *(const float4*)&A[(size_t)(m0 + ar) * K + k0 + ac];
        float4 bv = *(const float4*)&Bp[(size_t)(k0 + bk) * N + n0 + bn];
        if (FOLD) {
            float ss = sp[k0 + bk], tt = tp[k0 + bk];
            bv.x = fmaf(bv.x, ss, tt); bv.y = fmaf(bv.y, ss, tt);
            bv.z = fmaf(bv.z, ss, tt); bv.w = fmaf(bv.w, ss, tt);
        }
        __syncthreads();
        As[ac + 0][ar] = av.x; As[ac + 1][ar] = av.y;
        As[ac + 2][ar] = av.z; As[ac + 3][ar] = av.w;
        *(float4*)&Bs[bk][bn] = bv;
        __syncthreads();
#pragma unroll
        for (int kk = 0; kk < 8; kk++) {
            float a[8], bb[8];
            *(float4*)&a[0]  = *(const float4*)&As[kk][ty * 8];
            *(float4*)&a[4]  = *(const float4*)&As[kk][ty * 8 + 4];
            *(float4*)&bb[0] = *(const float4*)&Bs[kk][tx * 8];
            *(float4*)&bb[4] = *(const float4*)&Bs[kk][tx * 8 + 4];
#pragma unroll
            for (int i = 0; i < 8; i++)
#pragma unroll
                for (int j = 0; j < 8; j++)
                    acc[i][j] = fmaf(a[i], bb[j], acc[i][j]);
        }
    }

#pragma unroll
    for (int i = 0; i < 8; i++) {
        int m = m0 + ty * 8 + i;
        float bvv = bias[m];
        size_t base = (size_t)m * N + n0 + tx * 8;
#pragma unroll
        for (int v = 0; v < 2; v++) {
            float4 o;
            o.x = acc[i][v * 4 + 0] + bvv; o.y = acc[i][v * 4 + 1] + bvv;
            o.z = acc[i][v * 4 + 2] + bvv; o.w = acc[i][v * 4 + 3] + bvv;
            if (RESID) {
                float4 r = *(const float4*)&Rp[base + v * 4];
                o.x += r.x; o.y += r.y; o.z += r.z; o.w += r.w;
            }
            *(float4*)&Cp[base + v * 4] = o;
        }
    }
}

// ---------------- 3) flash v2b: static 48KB smem, pitch 64, v swizzled -------
// 128 threads: ty = tid>>4 (rows ty*8..+7), tx = tid&15 (keys/d tx*4..+3)
__global__ __launch_bounds__(128) void flash2_kernel()
{
    __shared__ float qd[64 * 64];   // q:  [d][row], pre-scaled
    __shared__ float kP[64 * 64];   // k:  [d][m]  -> later P: [row][m]
    __shared__ float vS[64 * 64];   // v^T: [m][d], float4-slot XOR swizzle by (m&15)

    int z = blockIdx.y, b = z / H_, h = z % H_;
    int l0 = blockIdx.x * 64;
    const float* qp = g_qkv + (size_t)b * 3 * C_ * L_ + (size_t)(h * D_) * L_;
    const float* kp = qp + (size_t)C_ * L_;
    const float* vp = kp + (size_t)C_ * L_;

    const int tid = threadIdx.x;
    const int ty = tid >> 4, tx = tid & 15;

    // q tile: [d][row], fold scale 0.125 (fill conflict-free: warp has fixed d)
    for (int e = tid; e < 4096; e += 128) {
        int d = e >> 6, r = e & 63;
        qd[d * 64 + r] = qp[(size_t)d * L_ + l0 + r] * 0.125f;
    }

    float out[8][4];
#pragma unroll
    for (int i = 0; i < 8; i++)
#pragma unroll
        for (int j = 0; j < 4; j++) out[i][j] = 0.f;
    float mx[8], sml[8];
#pragma unroll
    for (int i = 0; i < 8; i++) { mx[i] = -1e30f; sml[i] = 0.f; }

    for (int m0 = 0; m0 < L_; m0 += 64) {
        __syncthreads();   // prev PV done before overwriting kP / vS
        for (int e = tid; e < 4096; e += 128) {
            int d = e >> 6, m = e & 63;
            kP[d * 64 + m] = kp[(size_t)d * L_ + m0 + m];
            // v transposed store with float4-slot swizzle (4-way fill conflict)
            int slot = (d >> 2) ^ (m & 15);
            vS[m * 64 + slot * 4 + (d & 3)] = vp[(size_t)d * L_ + m0 + m];
        }
        __syncthreads();

        // ---- S = q . k^T  (8 rows x 4 keys per thread) ----
        float s[8][4];
#pragma unroll
        for (int i = 0; i < 8; i++)
#pragma unroll
            for (int j = 0; j < 4; j++) s[i][j] = 0.f;
        {
            const float4* qd4 = (const float4*)qd;
            const float4* kd4 = (const float4*)kP;
#pragma unroll 8
            for (int d = 0; d < 64; d++) {
                float4 k4 = kd4[d * 16 + tx];
                float4 qa = qd4[d * 16 + ty * 2];
                float4 qb = qd4[d * 16 + ty * 2 + 1];
                float qr0 = qa.x, qr1 = qa.y, qr2 = qa.z, qr3 = qa.w;
                float qr4 = qb.x, qr5 = qb.y, qr6 = qb.z, qr7 = qb.w;
                s[0][0] = fmaf(qr0, k4.x, s[0][0]); s[0][1] = fmaf(qr0, k4.y, s[0][1]);
                s[0][2] = fmaf(qr0, k4.z, s[0][2]); s[0][3] = fmaf(qr0, k4.w, s[0][3]);
                s[1][0] = fmaf(qr1, k4.x, s[1][0]); s[1][1] = fmaf(qr1, k4.y, s[1][1]);
                s[1][2] = fmaf(qr1, k4.z, s[1][2]); s[1][3] = fmaf(qr1, k4.w, s[1][3]);
                s[2][0] = fmaf(qr2, k4.x, s[2][0]); s[2][1] = fmaf(qr2, k4.y, s[2][1]);
                s[2][2] = fmaf(qr2, k4.z, s[2][2]); s[2][3] = fmaf(qr2, k4.w, s[2][3]);
                s[3][0] = fmaf(qr3, k4.x, s[3][0]); s[3][1] = fmaf(qr3, k4.y, s[3][1]);
                s[3][2] = fmaf(qr3, k4.z, s[3][2]); s[3][3] = fmaf(qr3, k4.w, s[3][3]);
                s[4][0] = fmaf(qr4, k4.x, s[4][0]); s[4][1] = fmaf(qr4, k4.y, s[4][1]);
                s[4][2] = fmaf(qr4, k4.z, s[4][2]); s[4][3] = fmaf(qr4, k4.w, s[4][3]);
                s[5][0] = fmaf(qr5, k4.x, s[5][0]); s[5][1] = fmaf(qr5, k4.y, s[5][1]);
                s[5][2] = fmaf(qr5, k4.z, s[5][2]); s[5][3] = fmaf(qr5, k4.w, s[5][3]);
                s[6][0] = fmaf(qr6, k4.x, s[6][0]); s[6][1] = fmaf(qr6, k4.y, s[6][1]);
                s[6][2] = fmaf(qr6, k4.z, s[6][2]); s[6][3] = fmaf(qr6, k4.w, s[6][3]);
                s[7][0] = fmaf(qr7, k4.x, s[7][0]); s[7][1] = fmaf(qr7, k4.y, s[7][1]);
                s[7][2] = fmaf(qr7, k4.z, s[7][2]); s[7][3] = fmaf(qr7, k4.w, s[7][3]);
            }
        }

        // ---- online softmax (row reductions across 16 tx lanes via shfl) ----
#pragma unroll
        for (int i = 0; i < 8; i++) {
            float tm = fmaxf(fmaxf(s[i][0], s[i][1]), fmaxf(s[i][2], s[i][3]));
            tm = fmaxf(tm, __shfl_xor_sync(0xffffffffu, tm, 1));
            tm = fmaxf(tm, __shfl_xor_sync(0xffffffffu, tm, 2));
            tm = fmaxf(tm, __shfl_xor_sync(0xffffffffu, tm, 4));
            tm = fmaxf(tm, __shfl_xor_sync(0xffffffffu, tm, 8));
            float nm = fmaxf(tm, mx[i]);
            float alpha = fast_exp(mx[i] - nm);
            mx[i] = nm;
            float p0 = fast_exp(s[i][0] - nm);
            float p1 = fast_exp(s[i][1] - nm);
            float p2 = fast_exp(s[i][2] - nm);
            float p3 = fast_exp(s[i][3] - nm);
            s[i][0] = p0; s[i][1] = p1; s[i][2] = p2; s[i][3] = p3;
            float ps = (p0 + p1) + (p2 + p3);
            ps += __shfl_xor_sync(0xffffffffu, ps, 1);
            ps += __shfl_xor_sync(0xffffffffu, ps, 2);
            ps += __shfl_xor_sync(0xffffffffu, ps, 4);
            ps += __shfl_xor_sync(0xffffffffu, ps, 8);
            sml[i] = fmaf(sml[i], alpha, ps);
            out[i][0] *= alpha; out[i][1] *= alpha;
            out[i][2] *= alpha; out[i][3] *= alpha;
        }
        __syncthreads();   // all warps done reading kP before P overwrite

        // ---- write P[row][m] into the (dead) k buffer ----
        {
            float4* Ps4 = (float4*)kP;
#pragma unroll
            for (int i = 0; i < 8; i++) {
                float4 pv;
                pv.x = s[i][0]; pv.y = s[i][1]; pv.z = s[i][2]; pv.w = s[i][3];
                Ps4[(ty * 8 + i) * 16 + tx] = pv;
            }
        }
        __syncthreads();

        // ---- out += P . V  (8 rows x 4 d per thread, 4 m per step) ----
        {
            const float4* Ps4 = (const float4*)kP;
            const float4* vS4 = (const float4*)vS;
#pragma unroll 4
            for (int mc = 0; mc < 16; mc++) {
                float4 pr0 = Ps4[(ty * 8 + 0) * 16 + mc];
                float4 pr1 = Ps4[(ty * 8 + 1) * 16 + mc];
                float4 pr2 = Ps4[(ty * 8 + 2) * 16 + mc];
                float4 pr3 = Ps4[(ty * 8 + 3) * 16 + mc];
                float4 pr4 = Ps4[(ty * 8 + 4) * 16 + mc];
                float4 pr5 = Ps4[(ty * 8 + 5) * 16 + mc];
                float4 pr6 = Ps4[(ty * 8 + 6) * 16 + mc];
                float4 pr7 = Ps4[(ty * 8 + 7) * 16 + mc];
#pragma unroll
                for (int mm = 0; mm < 4; mm++) {
                    int m = mc * 4 + mm;
                    float4 vf = vS4[m * 16 + (tx ^ (m & 15))];
                    float p0 = (mm == 0) ? pr0.x : (mm == 1) ? pr0.y : (mm == 2) ? pr0.z : pr0.w;
                    float p1 = (mm == 0) ? pr1.x : (mm == 1) ? pr1.y : (mm == 2) ? pr1.z : pr1.w;
                    float p2 = (mm == 0) ? pr2.x : (mm == 1) ? pr2.y : (mm == 2) ? pr2.z : pr2.w;
                    float p3 = (mm == 0) ? pr3.x : (mm == 1) ? pr3.y : (mm == 2) ? pr3.z : pr3.w;
                    float p4 = (mm == 0) ? pr4.x : (mm == 1) ? pr4.y : (mm == 2) ? pr4.z : pr4.w;
                    float p5 = (mm == 0) ? pr5.x : (mm == 1) ? pr5.y : (mm == 2) ? pr5.z : pr5.w;
                    float p6 = (mm == 0) ? pr6.x : (mm == 1) ? pr6.y : (mm == 2) ? pr6.z : pr6.w;
                    float p7 = (mm == 0) ? pr7.x : (mm == 1) ? pr7.y : (mm == 2) ? pr7.z : pr7.w;
                    out[0][0] = fmaf(p0, vf.x, out[0][0]); out[0][1] = fmaf(p0, vf.y, out[0][1]);
                    out[0][2] = fmaf(p0, vf.z, out[0][2]); out[0][3] = fmaf(p0, vf.w, out[0][3]);
                    out[1][0] = fmaf(p1, vf.x, out[1][0]); out[1][1] = fmaf(p1, vf.y, out[1][1]);
                    out[1][2] = fmaf(p1, vf.z, out[1][2]); out[1][3] = fmaf(p1, vf.w, out[1][3]);
                    out[2][0] = fmaf(p2, vf.x, out[2][0]); out[2][1] = fmaf(p2, vf.y, out[2][1]);
                    out[2][2] = fmaf(p2, vf.z, out[2][2]); out[2][3] = fmaf(p2, vf.w, out[2][3]);
                    out[3][0] = fmaf(p3, vf.x, out[3][0]); out[3][1] = fmaf(p3, vf.y, out[3][1]);
                    out[3][2] = fmaf(p3, vf.z, out[3][2]); out[3][3] = fmaf(p3, vf.w, out[3][3]);
                    out[4][0] = fmaf(p4, vf.x, out[4][0]); out[4][1] = fmaf(p4, vf.y, out[4][1]);
                    out[4][2] = fmaf(p4, vf.z, out[4][2]); out[4][3] = fmaf(p4, vf.w, out[4][3]);
                    out[5][0] = fmaf(p5, vf.x, out[5][0]); out[5][1] = fmaf(p5, vf.y, out[5][1]);
                    out[5][2] = fmaf(p5, vf.z, out[5][2]); out[5][3] = fmaf(p5, vf.w, out[5][3]);
                    out[6][0] = fmaf(p6, vf.x, out[6][0]); out[6][1] = fmaf(p6, vf.y, out[6][1]);
                    out[6][2] = fmaf(p6, vf.z, out[6][2]); out[6][3] = fmaf(p6, vf.w, out[6][3]);
                    out[7][0] = fmaf(p7, vf.x, out[7][0]); out[7][1] = fmaf(p7, vf.y, out[7][1]);
                    out[7][2] = fmaf(p7, vf.z, out[7][2]); out[7][3] = fmaf(p7, vf.w, out[7][3]);
                }
            }
        }
    }

    // ---- normalize + store att[d][l] ----
    float* op = g_att + (size_t)b * C_ * L_ + (size_t)(h * D_) * L_;
#pragma unroll
    for (int i = 0; i < 8; i++) {
        float inv = 1.0f / sml[i];
        int l = l0 + ty * 8 + i;
#pragma unroll
        for (int jd = 0; jd < 4; jd++) {
            int d = tx * 4 + jd;
            op[(size_t)d * L_ + l] = out[i][jd] * inv;
        }
    }
}

// ---------------- launch -----------------------------------------------------
extern "C" void kernel_launch(void* const* d_in, const int* in_sizes, int n_in,
                              void* d_out, int out_size)
{
    const float* x      = (const float*)d_in[0];
    const float* norm_w = (const float*)d_in[1];
    const float* norm_b = (const float*)d_in[2];
    const float* qkv_w  = (const float*)d_in[3];
    const float* qkv_b  = (const float*)d_in[4];
    const float* proj_w = (const float*)d_in[5];
    const float* proj_b = (const float*)d_in[6];
    float* out = (float*)d_out;

    float* qkv_ptr; cudaGetSymbolAddress((void**)&qkv_ptr, g_qkv);
    float* att_ptr; cudaGetSymbolAddress((void**)&att_ptr, g_att);

    gn_stats_kernel<<<B_ * G_, 256>>>(x, norm_w, norm_b);

    {
        dim3 grid(L_ / 128, (3 * C_) / 128, B_);
        sgemm_wx_kernel<true, false><<<grid, 256>>>(
            qkv_w, x, qkv_b, nullptr, qkv_ptr, 3 * C_, L_, C_);
    }

    {
        dim3 grid(L_ / 64, B_ * H_);
        flash2_kernel<<<grid, 128>>>();
    }

    {
        dim3 grid(L_ / 128, C_ / 128, B_);
        sgemm_wx_kernel<false, true><<<grid, 256>>>(
            proj_w, att_ptr, proj_b, x, out, C_, L_, C_);
    }
}